// round 14
// baseline (speedup 1.0000x reference)
#include <cuda_runtime.h>
#include <cstdint>

#define BB       8
#define NN       8192
#define NPOINT   1024
#define NSAMPLE  32
#define CFEAT    64
#define CIN0     67      // 3 + 64

#define FPS_BLKS   16                   // 2 CTAs (one cluster) per batch
#define MLP_BLOCKS 132                  // blocks 16..147
#define NWARPS_TOT (MLP_BLOCKS * 16)    // 2112 consumer warps

// ------------------------------------------------------------------
// scratch (no allocations allowed)
// ------------------------------------------------------------------
__device__ unsigned g_prog[BB * 32];    // per-batch FPS progress, 128B padded
__device__ unsigned g_mlp_ctr;          // work-steal counter (reset each run)

// ------------------------------------------------------------------
// packed f32x2 + sync helpers (Blackwell sm_103a)
// ------------------------------------------------------------------
__device__ __forceinline__ unsigned long long pk2(float lo, float hi) {
    unsigned long long r;
    asm("mov.b64 %0, {%1, %2};" : "=l"(r) : "f"(lo), "f"(hi));
    return r;
}
__device__ __forceinline__ void upk2(unsigned long long v, float& lo, float& hi) {
    asm("mov.b64 {%0, %1}, %2;" : "=f"(lo), "=f"(hi) : "l"(v));
}
__device__ __forceinline__ unsigned long long add2_(unsigned long long a, unsigned long long b) {
    unsigned long long r;
    asm("add.rn.f32x2 %0, %1, %2;" : "=l"(r) : "l"(a), "l"(b));
    return r;
}
__device__ __forceinline__ unsigned long long mul2_(unsigned long long a, unsigned long long b) {
    unsigned long long r;
    asm("mul.rn.f32x2 %0, %1, %2;" : "=l"(r) : "l"(a), "l"(b));
    return r;
}
__device__ __forceinline__ unsigned long long fma2_(unsigned long long a, unsigned long long b,
                                                    unsigned long long c) {
    unsigned long long r;
    asm("fma.rn.f32x2 %0, %1, %2, %3;" : "=l"(r) : "l"(a), "l"(b), "l"(c));
    return r;
}
__device__ __forceinline__ unsigned ld_acq32(const unsigned* p) {
    unsigned v;
    asm volatile("ld.acquire.gpu.b32 %0, [%1];" : "=r"(v) : "l"(p) : "memory");
    return v;
}
__device__ __forceinline__ void st_rel32(unsigned* p, unsigned v) {
    asm volatile("st.release.gpu.b32 [%0], %1;" :: "l"(p), "r"(v) : "memory");
}
__device__ __forceinline__ uint32_t smem_u32(const void* p) {
    uint32_t a;
    asm("{ .reg .u64 t; cvta.to.shared.u64 t, %1; cvt.u32.u64 %0, t; }" : "=r"(a) : "l"(p));
    return a;
}
__device__ __forceinline__ void mbar_init(uint32_t a, unsigned c) {
    asm volatile("mbarrier.init.shared.b64 [%0], %1;" :: "r"(a), "r"(c) : "memory");
}
__device__ __forceinline__ void remote_st64(uint32_t laddr, int peer, unsigned long long v) {
    asm volatile("{ .reg .b32 ra; mapa.shared::cluster.u32 ra, %0, %1;\n\t"
                 "st.shared::cluster.u64 [ra], %2; }"
                 :: "r"(laddr), "r"(peer), "l"(v) : "memory");
}
__device__ __forceinline__ void mbar_arrive_local(uint32_t a) {
    asm volatile("mbarrier.arrive.release.cluster.shared::cta.b64 _, [%0];"
                 :: "r"(a) : "memory");
}
__device__ __forceinline__ void mbar_arrive_remote(uint32_t a, int peer) {
    asm volatile("{ .reg .b32 ra; mapa.shared::cluster.u32 ra, %0, %1;\n\t"
                 "mbarrier.arrive.release.cluster.shared::cluster.b64 _, [ra]; }"
                 :: "r"(a), "r"(peer) : "memory");
}
__device__ __forceinline__ void mbar_wait_cluster(uint32_t a, unsigned par) {
    asm volatile("{ .reg .pred P;\n\t"
                 "W_%=: mbarrier.try_wait.parity.acquire.cluster.shared::cta.b64 P, [%0], %1, 0x989680;\n\t"
                 "@P bra D_%=;\n\t"
                 "bra W_%=;\n\t"
                 "D_%=: }"
                 :: "r"(a), "r"(par) : "memory");
}
#define CLUSTER_SYNC() do { \
    asm volatile("barrier.cluster.arrive.aligned;" ::: "memory"); \
    asm volatile("barrier.cluster.wait.aligned;" ::: "memory"); \
} while (0)

// ==================================================================
// Kernel 0: reset progress + steal counter.
// ==================================================================
__global__ void resetk()
{
    if (threadIdx.x < BB) g_prog[threadIdx.x * 32] = 0u;
    if (threadIdx.x == 0) g_mlp_ctr = NWARPS_TOT;
}

// ==================================================================
// Fused kernel, cluster dims (2,1,1):
//   blocks 0..15  : FPS producers — 2-CTA cluster per batch, each CTA
//                   owns 4096 points (8/thread), exchanges its CTA
//                   (max,idx) once per iter via DSMEM + mbarrier.
//                   Cross-CTA tiebreak: rank0 indices < rank1 indices,
//                   so strict > comparison preserves first-max-index.
//   blocks 16..147: persistent MLP consumers (unchanged from R13).
// ==================================================================
#define FPS_T 512
#define FPS_P 8                  // 4096 pts per CTA / 512 threads
#define MLP_T   512
#define RPITCH  67               // 67 % 32 = 3 -> 8 samples hit 8 banks
#define W0SL    (CIN0 * 16 + 4)  // 1076 floats per slice (skewed)
#define W1SL    (64 * 16 + 4)    // 1028
#define W2SL    (64 * 16 + 4)    // 1028

__global__ void __launch_bounds__(512, 1) __cluster_dims__(2, 1, 1)
fused_kernel(const float* __restrict__ xyz, const float* __restrict__ feat,
             const float* __restrict__ w0, const float* __restrict__ s0g, const float* __restrict__ b0g,
             const float* __restrict__ w1, const float* __restrict__ s1g, const float* __restrict__ b1g,
             const float* __restrict__ w2, const float* __restrict__ s2g, const float* __restrict__ b2g,
             float* __restrict__ newxyz, float* __restrict__ outfeat)
{
    extern __shared__ float sm[];

    if (blockIdx.x < FPS_BLKS) {
        // ================= FPS producer (2-CTA cluster per batch) ====
        float* sx = sm;
        float* sy = sm + NN;
        float* sz = sm + 2 * NN;
        unsigned* wv = (unsigned*)(sm + 3 * NN);            // [2][16]
        unsigned* wi = wv + 32;                             // [2][16]
        unsigned long long* es = (unsigned long long*)(wi + 32);  // [2 par][2 rank]
        unsigned long long* mbp = es + 4;                   // mbarrier

        const int r = blockIdx.x & 1;        // rank within cluster
        const int peer = r ^ 1;
        const int b = blockIdx.x >> 1;       // batch
        const float* bx = xyz + (size_t)b * NN * 3;
        float* out = newxyz + (size_t)b * NPOINT * 3;
        unsigned* prog = &g_prog[b * 32];
        const int t = threadIdx.x;
        const int lane = t & 31;
        const int warp = t >> 5;
        const uint32_t es_a = smem_u32(es);
        const uint32_t mb_a = smem_u32(mbp);

        // full batch xyz -> own smem (one-time; needed for winner lookup)
        for (int i = t; i < NN; i += FPS_T) {
            sx[i] = bx[3 * i + 0];
            sy[i] = bx[3 * i + 1];
            sz[i] = bx[3 * i + 2];
        }
        if (t == 0) mbar_init(mb_a, 2u);
        __syncthreads();
        CLUSTER_SYNC();   // peer barrier init + both CTAs ready

        const int gbase = r * (NN / 2) + t * FPS_P;  // this thread's 8 pts
        unsigned long long px2[FPS_P / 2], py2[FPS_P / 2], pz2[FPS_P / 2];
        float mind[FPS_P];
#pragma unroll
        for (int k = 0; k < FPS_P / 2; k++) {
            px2[k] = pk2(sx[gbase + 2 * k], sx[gbase + 2 * k + 1]);
            py2[k] = pk2(sy[gbase + 2 * k], sy[gbase + 2 * k + 1]);
            pz2[k] = pk2(sz[gbase + 2 * k], sz[gbase + 2 * k + 1]);
            mind[2 * k] = 1e10f;
            mind[2 * k + 1] = 1e10f;
        }

        float qx = sx[0], qy = sy[0], qz = sz[0];
        if (r == 0 && t == 0) { out[0] = qx; out[1] = qy; out[2] = qz; }

        unsigned ph = 0;
        for (int it = 1; it < NPOINT; it++) {
            const unsigned long long nqx = pk2(-qx, -qx);
            const unsigned long long nqy = pk2(-qy, -qy);
            const unsigned long long nqz = pk2(-qz, -qz);
            float vloc = -1.0f;
#pragma unroll
            for (int k = 0; k < FPS_P / 2; k++) {
                unsigned long long dx = add2_(px2[k], nqx);
                unsigned long long dy = add2_(py2[k], nqy);
                unsigned long long dz = add2_(pz2[k], nqz);
                unsigned long long d2 = add2_(add2_(mul2_(dx, dx), mul2_(dy, dy)),
                                              mul2_(dz, dz));
                float d0, d1;
                upk2(d2, d0, d1);
                float m0 = fminf(mind[2 * k], d0);
                float m1 = fminf(mind[2 * k + 1], d1);
                mind[2 * k] = m0;
                mind[2 * k + 1] = m1;
                vloc = fmaxf(vloc, fmaxf(m0, m1));
            }
            // first local index attaining the THREAD max (overlaps REDUX)
            unsigned idxl = 0xffffffffu;
#pragma unroll
            for (int j = FPS_P - 1; j >= 0; j--)
                if (mind[j] == vloc) idxl = gbase + j;

            unsigned vb = __float_as_uint(vloc);
            unsigned wmax = __reduce_max_sync(0xffffffffu, vb);
            unsigned act = __ballot_sync(0xffffffffu, vb == wmax);
            int src = __ffs(act) - 1;
            unsigned widx = __shfl_sync(0xffffffffu, idxl, src);

            const int par16 = (it & 1) << 4;
            if (lane == 0) { wv[par16 + warp] = wmax; wi[par16 + warp] = widx; }
            __syncthreads();

            unsigned bvv = wv[par16 + (lane & 15)];
            unsigned bii = wi[par16 + (lane & 15)];
            unsigned cmax = __reduce_max_sync(0xffffffffu, bvv);
            unsigned cidx = __reduce_min_sync(0xffffffffu,
                                              (bvv == cmax) ? bii : 0xffffffffu);

            // ---- cross-CTA exchange via DSMEM + mbarrier ----
            const int sl = it & 1;
            if (t == 0) {
                unsigned long long w = ((unsigned long long)cmax << 32) | cidx;
                es[sl * 2 + r] = w;                                 // own copy
                remote_st64(es_a + (uint32_t)((sl * 2 + r) * 8), peer, w);
                mbar_arrive_remote(mb_a, peer);
                mbar_arrive_local(mb_a);
            }
            mbar_wait_cluster(mb_a, ph);
            ph ^= 1u;

            unsigned long long w0 = es[sl * 2 + 0];
            unsigned long long w1 = es[sl * 2 + 1];
            unsigned v0 = (unsigned)(w0 >> 32), v1 = (unsigned)(w1 >> 32);
            // rank0 indices all < rank1 indices -> strict > keeps first idx
            unsigned bi = (v1 > v0) ? (unsigned)w1 : (unsigned)w0;

            qx = sx[bi]; qy = sy[bi]; qz = sz[bi];
            if (r == 0 && t == 0) {
                out[it * 3 + 0] = qx;
                out[it * 3 + 1] = qy;
                out[it * 3 + 2] = qz;
                if ((it & 7) == 7 || it == NPOINT - 1)
                    st_rel32(prog, (unsigned)it + 1u);
            }
        }
        return;
    }

    // ================= MLP consumer (R13, offsets updated) =========
    float* w0v = sm;                    // 4 slices x W0SL
    float* w1v = w0v + 4 * W0SL;        // 4 slices x W1SL
    float* w2v = w1v + 4 * W1SL;        // 8 slices x W2SL
    float* sc0 = w2v + 8 * W2SL;
    float* bi0 = sc0 + 64;
    float* sc1 = bi0 + 64;
    float* bi1 = sc1 + 64;
    float* sc2 = bi1 + 64;              // 128
    float* bi2 = sc2 + 128;             // 128
    float* xr  = bi2 + 128;             // 16 * 32 * RPITCH

    const int t = threadIdx.x;
    const int lane = t & 31;
    const int g = t >> 5;               // warp within block
    const int q = lane & 7;             // sample quad id (samples 4q..4q+3)
    const int s = lane >> 3;            // channel-slice id (0..3)

    for (int i = t; i < 4 * CIN0 * 16; i += MLP_T) {
        int sl = i / (CIN0 * 16), rr = i - sl * (CIN0 * 16);
        int c = rr >> 4, k = rr & 15;
        w0v[sl * W0SL + rr] = w0[(sl * 16 + k) * CIN0 + c];
    }
    for (int i = t; i < 4 * 64 * 16; i += MLP_T) {
        int sl = i >> 10, rr = i & 1023;
        int c = rr >> 4, k = rr & 15;
        w1v[sl * W1SL + rr] = w1[(sl * 16 + k) * 64 + c];
    }
    for (int i = t; i < 8 * 64 * 16; i += MLP_T) {
        int sl = i >> 10, rr = i & 1023;
        int c = rr >> 4, k = rr & 15;
        w2v[sl * W2SL + rr] = w2[(sl * 16 + k) * 64 + c];
    }
    if (t < 64)  { sc0[t] = s0g[t]; bi0[t] = b0g[t]; sc1[t] = s1g[t]; bi1[t] = b1g[t]; }
    if (t < 128) { sc2[t] = s2g[t]; bi2[t] = b2g[t]; }
    __syncthreads();

    float* xg = xr + g * 32 * RPITCH;
    int* idxbuf = (int*)xg;
    const int q2 = (q >> 2) & 1, q1 = (q >> 1) & 1, q0 = q & 1;

    unsigned u = (blockIdx.x - FPS_BLKS) * 16 + g;

    while (u < BB * NPOINT) {
        unsigned nxt;
        if (lane == 0) nxt = atomicAdd(&g_mlp_ctr, 1u);
        nxt = __shfl_sync(0xffffffffu, nxt, 0);

        const int sidx = (int)(u >> 3);       // s-major readiness order
        const int b    = (int)(u & 7);
        const int gi   = b * NPOINT + sidx;

        {
            const unsigned* pp = &g_prog[b * 32];
            unsigned pv = ld_acq32(pp);
            int slp = 128;
            while (pv <= (unsigned)sidx) {
                __nanosleep(slp);
                if (slp < 1024) slp <<= 1;
                pv = ld_acq32(pp);
            }
        }

        const float cx = newxyz[gi * 3 + 0];
        const float cy = newxyz[gi * 3 + 1];
        const float cz = newxyz[gi * 3 + 2];

        int myidx;
        {
            const float* bx = xyz + (size_t)b * NN * 3;
            const float R2 = (float)0.04;
            int cnt = 0, firstIdx = 0;
            for (int base = 0; base < NN; base += 32) {
                const int i = base + lane;
                float dx = __fsub_rn(bx[i * 3 + 0], cx);
                float dy = __fsub_rn(bx[i * 3 + 1], cy);
                float dz = __fsub_rn(bx[i * 3 + 2], cz);
                float d  = __fadd_rn(__fadd_rn(__fmul_rn(dx, dx), __fmul_rn(dy, dy)),
                                     __fmul_rn(dz, dz));
                bool in = d < R2;
                unsigned mask = __ballot_sync(0xffffffffu, in);
                if (mask) {
                    if (cnt == 0) firstIdx = base + (__ffs(mask) - 1);
                    if (in) {
                        int slot = cnt + __popc(mask & ((1u << lane) - 1u));
                        if (slot < NSAMPLE) idxbuf[slot] = i;
                    }
                    cnt += __popc(mask);
                    if (cnt >= NSAMPLE) break;
                }
            }
            __syncwarp();
            myidx = (lane < cnt) ? idxbuf[lane] : ((cnt > 0) ? firstIdx : 0);
            __syncwarp();
        }

#pragma unroll
        for (int j = 0; j < 4; j++) {
            const int n = 4 * q + j;
            const int pi = __shfl_sync(0xffffffffu, myidx, n);
            float* row = xg + n * RPITCH;
            const float* prow = xyz + ((size_t)b * NN + pi) * 3;
            row[0] = __fsub_rn(prow[0], cx);
            row[1] = __fsub_rn(prow[1], cy);
            row[2] = __fsub_rn(prow[2], cz);
            const float4* frow = (const float4*)(feat + ((size_t)b * NN + pi) * CFEAT);
#pragma unroll
            for (int k = 0; k < 16; k++) {
                float4 f = frow[k];
                row[3 + 4 * k + 0] = f.x;
                row[3 + 4 * k + 1] = f.y;
                row[3 + 4 * k + 2] = f.z;
                row[3 + 4 * k + 3] = f.w;
            }
        }
        __syncwarp();

        unsigned long long acc[32];
        const int chb = s * 16;

        // ---- layer 0: 67 -> 64 ----
        {
            const float* wb = w0v + s * W0SL;
#pragma unroll
            for (int i = 0; i < 32; i++) acc[i] = 0ull;
#pragma unroll 1
            for (int c = 0; c < CIN0; c++) {
                const ulonglong2* wr = (const ulonglong2*)(wb + c * 16);
                ulonglong2 wA = wr[0], wB = wr[1];
                unsigned long long x0 = pk2(xg[(4 * q + 0) * RPITCH + c], xg[(4 * q + 0) * RPITCH + c]);
                unsigned long long x1 = pk2(xg[(4 * q + 1) * RPITCH + c], xg[(4 * q + 1) * RPITCH + c]);
                unsigned long long x2 = pk2(xg[(4 * q + 2) * RPITCH + c], xg[(4 * q + 2) * RPITCH + c]);
                unsigned long long x3 = pk2(xg[(4 * q + 3) * RPITCH + c], xg[(4 * q + 3) * RPITCH + c]);
                acc[0]  = fma2_(x0, wA.x, acc[0]);  acc[1]  = fma2_(x0, wA.y, acc[1]);
                acc[2]  = fma2_(x0, wB.x, acc[2]);  acc[3]  = fma2_(x0, wB.y, acc[3]);
                acc[8]  = fma2_(x1, wA.x, acc[8]);  acc[9]  = fma2_(x1, wA.y, acc[9]);
                acc[10] = fma2_(x1, wB.x, acc[10]); acc[11] = fma2_(x1, wB.y, acc[11]);
                acc[16] = fma2_(x2, wA.x, acc[16]); acc[17] = fma2_(x2, wA.y, acc[17]);
                acc[18] = fma2_(x2, wB.x, acc[18]); acc[19] = fma2_(x2, wB.y, acc[19]);
                acc[24] = fma2_(x3, wA.x, acc[24]); acc[25] = fma2_(x3, wA.y, acc[25]);
                acc[26] = fma2_(x3, wB.x, acc[26]); acc[27] = fma2_(x3, wB.y, acc[27]);
                const ulonglong2* wr2 = (const ulonglong2*)(wb + c * 16 + 8);
                ulonglong2 wC = wr2[0], wD = wr2[1];
                acc[4]  = fma2_(x0, wC.x, acc[4]);  acc[5]  = fma2_(x0, wC.y, acc[5]);
                acc[6]  = fma2_(x0, wD.x, acc[6]);  acc[7]  = fma2_(x0, wD.y, acc[7]);
                acc[12] = fma2_(x1, wC.x, acc[12]); acc[13] = fma2_(x1, wC.y, acc[13]);
                acc[14] = fma2_(x1, wD.x, acc[14]); acc[15] = fma2_(x1, wD.y, acc[15]);
                acc[20] = fma2_(x2, wC.x, acc[20]); acc[21] = fma2_(x2, wC.y, acc[21]);
                acc[22] = fma2_(x2, wD.x, acc[22]); acc[23] = fma2_(x2, wD.y, acc[23]);
                acc[28] = fma2_(x3, wC.x, acc[28]); acc[29] = fma2_(x3, wC.y, acc[29]);
                acc[30] = fma2_(x3, wD.x, acc[30]); acc[31] = fma2_(x3, wD.y, acc[31]);
            }
            __syncwarp();
#pragma unroll
            for (int j = 0; j < 4; j++) {
                float* row = xg + (4 * q + j) * RPITCH;
#pragma unroll
                for (int u2 = 0; u2 < 8; u2++) {
                    float a0, a1;
                    upk2(acc[j * 8 + u2], a0, a1);
                    int oc = chb + 2 * u2;
                    float v0 = __fadd_rn(__fmul_rn(a0, sc0[oc]),     bi0[oc]);
                    float v1 = __fadd_rn(__fmul_rn(a1, sc0[oc + 1]), bi0[oc + 1]);
                    row[oc]     = fmaxf(v0, 0.0f);
                    row[oc + 1] = fmaxf(v1, 0.0f);
                }
            }
            __syncwarp();
        }

        // ---- layer 1: 64 -> 64 ----
        {
            const float* wb = w1v + s * W1SL;
#pragma unroll
            for (int i = 0; i < 32; i++) acc[i] = 0ull;
#pragma unroll 1
            for (int c = 0; c < 64; c++) {
                const ulonglong2* wr = (const ulonglong2*)(wb + c * 16);
                ulonglong2 wA = wr[0], wB = wr[1];
                unsigned long long x0 = pk2(xg[(4 * q + 0) * RPITCH + c], xg[(4 * q + 0) * RPITCH + c]);
                unsigned long long x1 = pk2(xg[(4 * q + 1) * RPITCH + c], xg[(4 * q + 1) * RPITCH + c]);
                unsigned long long x2 = pk2(xg[(4 * q + 2) * RPITCH + c], xg[(4 * q + 2) * RPITCH + c]);
                unsigned long long x3 = pk2(xg[(4 * q + 3) * RPITCH + c], xg[(4 * q + 3) * RPITCH + c]);
                acc[0]  = fma2_(x0, wA.x, acc[0]);  acc[1]  = fma2_(x0, wA.y, acc[1]);
                acc[2]  = fma2_(x0, wB.x, acc[2]);  acc[3]  = fma2_(x0, wB.y, acc[3]);
                acc[8]  = fma2_(x1, wA.x, acc[8]);  acc[9]  = fma2_(x1, wA.y, acc[9]);
                acc[10] = fma2_(x1, wB.x, acc[10]); acc[11] = fma2_(x1, wB.y, acc[11]);
                acc[16] = fma2_(x2, wA.x, acc[16]); acc[17] = fma2_(x2, wA.y, acc[17]);
                acc[18] = fma2_(x2, wB.x, acc[18]); acc[19] = fma2_(x2, wB.y, acc[19]);
                acc[24] = fma2_(x3, wA.x, acc[24]); acc[25] = fma2_(x3, wA.y, acc[25]);
                acc[26] = fma2_(x3, wB.x, acc[26]); acc[27] = fma2_(x3, wB.y, acc[27]);
                const ulonglong2* wr2 = (const ulonglong2*)(wb + c * 16 + 8);
                ulonglong2 wC = wr2[0], wD = wr2[1];
                acc[4]  = fma2_(x0, wC.x, acc[4]);  acc[5]  = fma2_(x0, wC.y, acc[5]);
                acc[6]  = fma2_(x0, wD.x, acc[6]);  acc[7]  = fma2_(x0, wD.y, acc[7]);
                acc[12] = fma2_(x1, wC.x, acc[12]); acc[13] = fma2_(x1, wC.y, acc[13]);
                acc[14] = fma2_(x1, wD.x, acc[14]); acc[15] = fma2_(x1, wD.y, acc[15]);
                acc[20] = fma2_(x2, wC.x, acc[20]); acc[21] = fma2_(x2, wC.y, acc[21]);
                acc[22] = fma2_(x2, wD.x, acc[22]); acc[23] = fma2_(x2, wD.y, acc[23]);
                acc[28] = fma2_(x3, wC.x, acc[28]); acc[29] = fma2_(x3, wC.y, acc[29]);
                acc[30] = fma2_(x3, wD.x, acc[30]); acc[31] = fma2_(x3, wD.y, acc[31]);
            }
            __syncwarp();
#pragma unroll
            for (int j = 0; j < 4; j++) {
                float* row = xg + (4 * q + j) * RPITCH;
#pragma unroll
                for (int u2 = 0; u2 < 8; u2++) {
                    float a0, a1;
                    upk2(acc[j * 8 + u2], a0, a1);
                    int oc = chb + 2 * u2;
                    float v0 = __fadd_rn(__fmul_rn(a0, sc1[oc]),     bi1[oc]);
                    float v1 = __fadd_rn(__fmul_rn(a1, sc1[oc + 1]), bi1[oc + 1]);
                    row[oc]     = fmaxf(v0, 0.0f);
                    row[oc + 1] = fmaxf(v1, 0.0f);
                }
            }
            __syncwarp();
        }

        // ---- layer 2: 64 -> 128 in 2 rounds; reduce-scatter maxpool ----
        const size_t outbase = (size_t)b * 128 * NPOINT + sidx;
#pragma unroll 1
        for (int r = 0; r < 2; r++) {
            const int p = s + 4 * r;
            const float* wb = w2v + p * W2SL;
#pragma unroll
            for (int i = 0; i < 32; i++) acc[i] = 0ull;
#pragma unroll 1
            for (int c = 0; c < 64; c++) {
                const ulonglong2* wr = (const ulonglong2*)(wb + c * 16);
                ulonglong2 wA = wr[0], wB = wr[1];
                unsigned long long x0 = pk2(xg[(4 * q + 0) * RPITCH + c], xg[(4 * q + 0) * RPITCH + c]);
                unsigned long long x1 = pk2(xg[(4 * q + 1) * RPITCH + c], xg[(4 * q + 1) * RPITCH + c]);
                unsigned long long x2 = pk2(xg[(4 * q + 2) * RPITCH + c], xg[(4 * q + 2) * RPITCH + c]);
                unsigned long long x3 = pk2(xg[(4 * q + 3) * RPITCH + c], xg[(4 * q + 3) * RPITCH + c]);
                acc[0]  = fma2_(x0, wA.x, acc[0]);  acc[1]  = fma2_(x0, wA.y, acc[1]);
                acc[2]  = fma2_(x0, wB.x, acc[2]);  acc[3]  = fma2_(x0, wB.y, acc[3]);
                acc[8]  = fma2_(x1, wA.x, acc[8]);  acc[9]  = fma2_(x1, wA.y, acc[9]);
                acc[10] = fma2_(x1, wB.x, acc[10]); acc[11] = fma2_(x1, wB.y, acc[11]);
                acc[16] = fma2_(x2, wA.x, acc[16]); acc[17] = fma2_(x2, wA.y, acc[17]);
                acc[18] = fma2_(x2, wB.x, acc[18]); acc[19] = fma2_(x2, wB.y, acc[19]);
                acc[24] = fma2_(x3, wA.x, acc[24]); acc[25] = fma2_(x3, wA.y, acc[25]);
                acc[26] = fma2_(x3, wB.x, acc[26]); acc[27] = fma2_(x3, wB.y, acc[27]);
                const ulonglong2* wr2 = (const ulonglong2*)(wb + c * 16 + 8);
                ulonglong2 wC = wr2[0], wD = wr2[1];
                acc[4]  = fma2_(x0, wC.x, acc[4]);  acc[5]  = fma2_(x0, wC.y, acc[5]);
                acc[6]  = fma2_(x0, wD.x, acc[6]);  acc[7]  = fma2_(x0, wD.y, acc[7]);
                acc[12] = fma2_(x1, wC.x, acc[12]); acc[13] = fma2_(x1, wC.y, acc[13]);
                acc[14] = fma2_(x1, wD.x, acc[14]); acc[15] = fma2_(x1, wD.y, acc[15]);
                acc[20] = fma2_(x2, wC.x, acc[20]); acc[21] = fma2_(x2, wC.y, acc[21]);
                acc[22] = fma2_(x2, wD.x, acc[22]); acc[23] = fma2_(x2, wD.y, acc[23]);
                acc[28] = fma2_(x3, wC.x, acc[28]); acc[29] = fma2_(x3, wC.y, acc[29]);
                acc[30] = fma2_(x3, wD.x, acc[30]); acc[31] = fma2_(x3, wD.y, acc[31]);
            }
            float vm[16];
#pragma unroll
            for (int u2 = 0; u2 < 8; u2++) {
                int oc = p * 16 + 2 * u2;
                float scA = sc2[oc], biA = bi2[oc], scB = sc2[oc + 1], biB = bi2[oc + 1];
                float m0 = 0.0f, m1 = 0.0f;
#pragma unroll
                for (int j = 0; j < 4; j++) {
                    float a0, a1;
                    upk2(acc[j * 8 + u2], a0, a1);
                    float v0 = __fadd_rn(__fmul_rn(a0, scA), biA);
                    float v1 = __fadd_rn(__fmul_rn(a1, scB), biB);
                    m0 = fmaxf(m0, fmaxf(v0, 0.0f));
                    m1 = fmaxf(m1, fmaxf(v1, 0.0f));
                }
                vm[2 * u2] = m0; vm[2 * u2 + 1] = m1;
            }
            float B8[8];
#pragma unroll
            for (int i = 0; i < 8; i++) {
                float snd = q2 ? vm[i] : vm[8 + i];
                float got = __shfl_xor_sync(0xffffffffu, snd, 4);
                float kp  = q2 ? vm[8 + i] : vm[i];
                B8[i] = fmaxf(kp, got);
            }
            float C4[4];
#pragma unroll
            for (int i = 0; i < 4; i++) {
                float snd = q1 ? B8[i] : B8[4 + i];
                float got = __shfl_xor_sync(0xffffffffu, snd, 2);
                float kp  = q1 ? B8[4 + i] : B8[i];
                C4[i] = fmaxf(kp, got);
            }
            float D0, D1;
            {
                float snd = q0 ? C4[0] : C4[2];
                float got = __shfl_xor_sync(0xffffffffu, snd, 1);
                float kp  = q0 ? C4[2] : C4[0];
                D0 = fmaxf(kp, got);
                snd = q0 ? C4[1] : C4[3];
                got = __shfl_xor_sync(0xffffffffu, snd, 1);
                kp  = q0 ? C4[3] : C4[1];
                D1 = fmaxf(kp, got);
            }
            const int ch = p * 16 + 2 * q;
            outfeat[outbase + (size_t)ch * NPOINT]       = D0;
            outfeat[outbase + (size_t)(ch + 1) * NPOINT] = D1;
        }

        u = nxt;
    }
}

// ==================================================================
// launch
// ==================================================================
extern "C" void kernel_launch(void* const* d_in, const int* in_sizes, int n_in,
                              void* d_out, int out_size)
{
    (void)in_sizes; (void)n_in; (void)out_size;
    const float* xyz  = (const float*)d_in[0];
    const float* feat = (const float*)d_in[1];
    const float* w0 = (const float*)d_in[2];
    const float* s0 = (const float*)d_in[3];
    const float* b0 = (const float*)d_in[4];
    const float* w1 = (const float*)d_in[5];
    const float* s1 = (const float*)d_in[6];
    const float* b1 = (const float*)d_in[7];
    const float* w2 = (const float*)d_in[8];
    const float* s2 = (const float*)d_in[9];
    const float* b2 = (const float*)d_in[10];

    float* out     = (float*)d_out;
    float* newxyz  = out;                            // (B, NPOINT, 3)
    float* outfeat = out + (size_t)BB * NPOINT * 3;  // (B, 128, NPOINT)

    const int FUSED_SMEM = (4 * W0SL + 4 * W1SL + 8 * W2SL + 512 +
                            16 * 32 * RPITCH) * 4;   // ~205,824 B
    cudaFuncSetAttribute(fused_kernel, cudaFuncAttributeMaxDynamicSharedMemorySize,
                         FUSED_SMEM);

    resetk<<<1, 32>>>();
    fused_kernel<<<FPS_BLKS + MLP_BLOCKS, 512, FUSED_SMEM>>>(
        xyz, feat, w0, s0, b0, w1, s1, b1, w2, s2, b2, newxyz, outfeat);
}

// round 15
// speedup vs baseline: 1.5346x; 1.5346x over previous
#include <cuda_runtime.h>
#include <cstdint>

#define BB       8
#define NN       8192
#define NPOINT   1024
#define NSAMPLE  32
#define CFEAT    64
#define CIN0     67      // 3 + 64

#define MLP_BLOCKS 140                  // blocks 8..147 of the fused grid
#define NWARPS_TOT (MLP_BLOCKS * 16)    // 2240 consumer warps

// ------------------------------------------------------------------
// scratch (no allocations allowed)
// ------------------------------------------------------------------
__device__ unsigned g_prog[BB * 32];    // per-batch FPS progress, 128B padded
__device__ unsigned g_mlp_ctr;          // work-steal counter (reset each run)

// ------------------------------------------------------------------
// packed f32x2 helpers (Blackwell sm_103a) — add/mul/fma only
// ------------------------------------------------------------------
__device__ __forceinline__ unsigned long long pk2(float lo, float hi) {
    unsigned long long r;
    asm("mov.b64 %0, {%1, %2};" : "=l"(r) : "f"(lo), "f"(hi));
    return r;
}
__device__ __forceinline__ void upk2(unsigned long long v, float& lo, float& hi) {
    asm("mov.b64 {%0, %1}, %2;" : "=f"(lo), "=f"(hi) : "l"(v));
}
__device__ __forceinline__ unsigned long long add2_(unsigned long long a, unsigned long long b) {
    unsigned long long r;
    asm("add.rn.f32x2 %0, %1, %2;" : "=l"(r) : "l"(a), "l"(b));
    return r;
}
__device__ __forceinline__ unsigned long long mul2_(unsigned long long a, unsigned long long b) {
    unsigned long long r;
    asm("mul.rn.f32x2 %0, %1, %2;" : "=l"(r) : "l"(a), "l"(b));
    return r;
}
__device__ __forceinline__ unsigned long long fma2_(unsigned long long a, unsigned long long b,
                                                    unsigned long long c) {
    unsigned long long r;
    asm("fma.rn.f32x2 %0, %1, %2, %3;" : "=l"(r) : "l"(a), "l"(b), "l"(c));
    return r;
}
__device__ __forceinline__ unsigned ld_acq32(const unsigned* p) {
    unsigned v;
    asm volatile("ld.acquire.gpu.b32 %0, [%1];" : "=r"(v) : "l"(p) : "memory");
    return v;
}
__device__ __forceinline__ void st_rel32(unsigned* p, unsigned v) {
    asm volatile("st.release.gpu.b32 [%0], %1;" :: "l"(p), "r"(v) : "memory");
}

// ==================================================================
// Kernel 0: reset progress + steal counter (graph replays would
// otherwise see stale g_prog and read the poisoned output buffer).
// ==================================================================
__global__ void resetk()
{
    if (threadIdx.x < BB) g_prog[threadIdx.x * 32] = 0u;
    if (threadIdx.x == 0) g_mlp_ctr = NWARPS_TOT;
}

// ==================================================================
// Fused kernel (R13 structure — proven 630 µs):
//   blocks 0..7   : FPS producers, single-CTA per batch.
//   blocks 8..147 : persistent MLP consumer warps.
// R15 trims: block-combine index pick via ballot/ffs/shfl (lanes
// mirror warps in index order, so lowest lane attaining the block
// max holds the lowest index); progress published every 4 iters.
// ==================================================================
#define FPS_T 512
#define FPS_P (NN / FPS_T)   // 16
#define MLP_T   512
#define RPITCH  67               // 67 % 32 = 3 -> 8 samples hit 8 banks
#define W0SL    (CIN0 * 16 + 4)  // 1076 floats per slice (skewed)
#define W1SL    (64 * 16 + 4)    // 1028
#define W2SL    (64 * 16 + 4)    // 1028

__global__ void __launch_bounds__(512, 1)
fused_kernel(const float* __restrict__ xyz, const float* __restrict__ feat,
             const float* __restrict__ w0, const float* __restrict__ s0g, const float* __restrict__ b0g,
             const float* __restrict__ w1, const float* __restrict__ s1g, const float* __restrict__ b1g,
             const float* __restrict__ w2, const float* __restrict__ s2g, const float* __restrict__ b2g,
             float* __restrict__ newxyz, float* __restrict__ outfeat)
{
    extern __shared__ float sm[];

    if (blockIdx.x < BB) {
        // ================= FPS producer =================
        float* sx = sm;
        float* sy = sm + NN;
        float* sz = sm + 2 * NN;
        unsigned* wv = (unsigned*)(sm + 3 * NN);   // [2][16]
        unsigned* wi = wv + 32;                    // [2][16]

        const int b = blockIdx.x;
        const float* bx = xyz + (size_t)b * NN * 3;
        float* out = newxyz + (size_t)b * NPOINT * 3;
        unsigned* prog = &g_prog[b * 32];
        const int t = threadIdx.x;
        const int lane = t & 31;
        const int warp = t >> 5;

        unsigned long long px2[FPS_P / 2], py2[FPS_P / 2], pz2[FPS_P / 2];
        float mind[FPS_P];
#pragma unroll
        for (int k = 0; k < FPS_P / 2; k++) {
            int i0 = t * FPS_P + 2 * k;
            int i1 = i0 + 1;
            float x0 = bx[i0 * 3 + 0], y0 = bx[i0 * 3 + 1], z0 = bx[i0 * 3 + 2];
            float x1 = bx[i1 * 3 + 0], y1 = bx[i1 * 3 + 1], z1 = bx[i1 * 3 + 2];
            px2[k] = pk2(x0, x1); py2[k] = pk2(y0, y1); pz2[k] = pk2(z0, z1);
            sx[i0] = x0; sy[i0] = y0; sz[i0] = z0;
            sx[i1] = x1; sy[i1] = y1; sz[i1] = z1;
            mind[2 * k] = 1e10f; mind[2 * k + 1] = 1e10f;
        }
        __syncthreads();

        float qx = sx[0], qy = sy[0], qz = sz[0];
        if (t == 0) { out[0] = qx; out[1] = qy; out[2] = qz; }

        for (int it = 1; it < NPOINT; it++) {
            const unsigned long long nqx = pk2(-qx, -qx);
            const unsigned long long nqy = pk2(-qy, -qy);
            const unsigned long long nqz = pk2(-qz, -qz);
            float vloc = -1.0f;
#pragma unroll
            for (int k = 0; k < FPS_P / 2; k++) {
                unsigned long long dx = add2_(px2[k], nqx);
                unsigned long long dy = add2_(py2[k], nqy);
                unsigned long long dz = add2_(pz2[k], nqz);
                unsigned long long d2 = add2_(add2_(mul2_(dx, dx), mul2_(dy, dy)),
                                              mul2_(dz, dz));
                float d0, d1;
                upk2(d2, d0, d1);
                float m0 = fminf(mind[2 * k], d0);
                float m1 = fminf(mind[2 * k + 1], d1);
                mind[2 * k] = m0;
                mind[2 * k + 1] = m1;
                vloc = fmaxf(vloc, fmaxf(m0, m1));
            }
            // first local index attaining the THREAD max (overlaps REDUX)
            unsigned idxl = 0xffffffffu;
#pragma unroll
            for (int j = FPS_P - 1; j >= 0; j--)
                if (mind[j] == vloc) idxl = t * FPS_P + j;

            unsigned vb = __float_as_uint(vloc);
            unsigned wmax = __reduce_max_sync(0xffffffffu, vb);
            unsigned act = __ballot_sync(0xffffffffu, vb == wmax);
            int src = __ffs(act) - 1;
            unsigned widx = __shfl_sync(0xffffffffu, idxl, src);

            const int par = (it & 1) << 4;
            if (lane == 0) { wv[par + warp] = wmax; wi[par + warp] = widx; }
            __syncthreads();

            unsigned bvv = wv[par + (lane & 15)];
            unsigned bii = wi[par + (lane & 15)];
            unsigned vmax = __reduce_max_sync(0xffffffffu, bvv);
            // lanes mirror warps in index order -> lowest lane with
            // bvv==vmax holds the lowest (first) index
            unsigned bact = __ballot_sync(0xffffffffu, bvv == vmax);
            int bsrc = __ffs(bact) - 1;
            unsigned bi = __shfl_sync(0xffffffffu, bii, bsrc);

            qx = sx[bi]; qy = sy[bi]; qz = sz[bi];
            if (t == 0) {
                out[it * 3 + 0] = qx;
                out[it * 3 + 1] = qy;
                out[it * 3 + 2] = qz;
                // batched release: fence off the per-iter critical path
                if ((it & 3) == 3 || it == NPOINT - 1)
                    st_rel32(prog, (unsigned)it + 1u);
            }
        }
        return;
    }

    // ================= MLP consumer =================
    float* w0v = sm;                    // 4 slices x W0SL
    float* w1v = w0v + 4 * W0SL;        // 4 slices x W1SL
    float* w2v = w1v + 4 * W1SL;        // 8 slices x W2SL
    float* sc0 = w2v + 8 * W2SL;
    float* bi0 = sc0 + 64;
    float* sc1 = bi0 + 64;
    float* bi1 = sc1 + 64;
    float* sc2 = bi1 + 64;              // 128
    float* bi2 = sc2 + 128;             // 128
    float* xr  = bi2 + 128;             // 16 * 32 * RPITCH

    const int t = threadIdx.x;
    const int lane = t & 31;
    const int g = t >> 5;               // warp within block
    const int q = lane & 7;             // sample quad id (samples 4q..4q+3)
    const int s = lane >> 3;            // channel-slice id (0..3)

    // ---- weight load: slice-major [slice][c][16] with +4 skew ----
    for (int i = t; i < 4 * CIN0 * 16; i += MLP_T) {
        int sl = i / (CIN0 * 16), r = i - sl * (CIN0 * 16);
        int c = r >> 4, k = r & 15;
        w0v[sl * W0SL + r] = w0[(sl * 16 + k) * CIN0 + c];
    }
    for (int i = t; i < 4 * 64 * 16; i += MLP_T) {
        int sl = i >> 10, r = i & 1023;
        int c = r >> 4, k = r & 15;
        w1v[sl * W1SL + r] = w1[(sl * 16 + k) * 64 + c];
    }
    for (int i = t; i < 8 * 64 * 16; i += MLP_T) {
        int sl = i >> 10, r = i & 1023;
        int c = r >> 4, k = r & 15;
        w2v[sl * W2SL + r] = w2[(sl * 16 + k) * 64 + c];
    }
    if (t < 64)  { sc0[t] = s0g[t]; bi0[t] = b0g[t]; sc1[t] = s1g[t]; bi1[t] = b1g[t]; }
    if (t < 128) { sc2[t] = s2g[t]; bi2[t] = b2g[t]; }
    __syncthreads();

    float* xg = xr + g * 32 * RPITCH;
    int* idxbuf = (int*)xg;             // 32 ints, used before gather overwrites
    const int q2 = (q >> 2) & 1, q1 = (q >> 1) & 1, q0 = q & 1;

    unsigned u = (blockIdx.x - BB) * 16 + g;   // initial unit = global warp id

    while (u < BB * NPOINT) {
        // prefetch next steal (latency hidden behind this unit)
        unsigned nxt;
        if (lane == 0) nxt = atomicAdd(&g_mlp_ctr, 1u);
        nxt = __shfl_sync(0xffffffffu, nxt, 0);

        const int sidx = (int)(u >> 3);       // s-major readiness order
        const int b    = (int)(u & 7);
        const int gi   = b * NPOINT + sidx;

        // ---- wait for FPS(b) to publish center sidx (backoff poll) ----
        {
            const unsigned* pp = &g_prog[b * 32];
            unsigned pv = ld_acq32(pp);
            int slp = 128;
            while (pv <= (unsigned)sidx) {
                __nanosleep(slp);
                if (slp < 1024) slp <<= 1;
                pv = ld_acq32(pp);
            }
        }

        const float cx = newxyz[gi * 3 + 0];
        const float cy = newxyz[gi * 3 + 1];
        const float cz = newxyz[gi * 3 + 2];

        // ---- in-warp ball query (bit-exact mask arithmetic) ----
        int myidx;
        {
            const float* bx = xyz + (size_t)b * NN * 3;
            const float R2 = (float)0.04;
            int cnt = 0, firstIdx = 0;
            for (int base = 0; base < NN; base += 32) {
                const int i = base + lane;
                float dx = __fsub_rn(bx[i * 3 + 0], cx);
                float dy = __fsub_rn(bx[i * 3 + 1], cy);
                float dz = __fsub_rn(bx[i * 3 + 2], cz);
                float d  = __fadd_rn(__fadd_rn(__fmul_rn(dx, dx), __fmul_rn(dy, dy)),
                                     __fmul_rn(dz, dz));
                bool in = d < R2;
                unsigned mask = __ballot_sync(0xffffffffu, in);
                if (mask) {
                    if (cnt == 0) firstIdx = base + (__ffs(mask) - 1);
                    if (in) {
                        int slot = cnt + __popc(mask & ((1u << lane) - 1u));
                        if (slot < NSAMPLE) idxbuf[slot] = i;
                    }
                    cnt += __popc(mask);
                    if (cnt >= NSAMPLE) break;
                }
            }
            __syncwarp();
            myidx = (lane < cnt) ? idxbuf[lane] : ((cnt > 0) ? firstIdx : 0);
            __syncwarp();   // all reads done before gather overwrites idxbuf
        }

        // ---- gather: this thread fills rows of its 4 samples ----
#pragma unroll
        for (int j = 0; j < 4; j++) {
            const int n = 4 * q + j;
            const int pi = __shfl_sync(0xffffffffu, myidx, n);
            float* row = xg + n * RPITCH;
            const float* prow = xyz + ((size_t)b * NN + pi) * 3;
            row[0] = __fsub_rn(prow[0], cx);
            row[1] = __fsub_rn(prow[1], cy);
            row[2] = __fsub_rn(prow[2], cz);
            const float4* frow = (const float4*)(feat + ((size_t)b * NN + pi) * CFEAT);
#pragma unroll
            for (int k = 0; k < 16; k++) {
                float4 f = frow[k];
                row[3 + 4 * k + 0] = f.x;
                row[3 + 4 * k + 1] = f.y;
                row[3 + 4 * k + 2] = f.z;
                row[3 + 4 * k + 3] = f.w;
            }
        }
        __syncwarp();

        unsigned long long acc[32];
        const int chb = s * 16;

        // ---- layer 0: 67 -> 64 ----
        {
            const float* wb = w0v + s * W0SL;
#pragma unroll
            for (int i = 0; i < 32; i++) acc[i] = 0ull;
#pragma unroll 1
            for (int c = 0; c < CIN0; c++) {
                const ulonglong2* wr = (const ulonglong2*)(wb + c * 16);
                ulonglong2 wA = wr[0], wB = wr[1];
                unsigned long long x0 = pk2(xg[(4 * q + 0) * RPITCH + c], xg[(4 * q + 0) * RPITCH + c]);
                unsigned long long x1 = pk2(xg[(4 * q + 1) * RPITCH + c], xg[(4 * q + 1) * RPITCH + c]);
                unsigned long long x2 = pk2(xg[(4 * q + 2) * RPITCH + c], xg[(4 * q + 2) * RPITCH + c]);
                unsigned long long x3 = pk2(xg[(4 * q + 3) * RPITCH + c], xg[(4 * q + 3) * RPITCH + c]);
                acc[0]  = fma2_(x0, wA.x, acc[0]);  acc[1]  = fma2_(x0, wA.y, acc[1]);
                acc[2]  = fma2_(x0, wB.x, acc[2]);  acc[3]  = fma2_(x0, wB.y, acc[3]);
                acc[8]  = fma2_(x1, wA.x, acc[8]);  acc[9]  = fma2_(x1, wA.y, acc[9]);
                acc[10] = fma2_(x1, wB.x, acc[10]); acc[11] = fma2_(x1, wB.y, acc[11]);
                acc[16] = fma2_(x2, wA.x, acc[16]); acc[17] = fma2_(x2, wA.y, acc[17]);
                acc[18] = fma2_(x2, wB.x, acc[18]); acc[19] = fma2_(x2, wB.y, acc[19]);
                acc[24] = fma2_(x3, wA.x, acc[24]); acc[25] = fma2_(x3, wA.y, acc[25]);
                acc[26] = fma2_(x3, wB.x, acc[26]); acc[27] = fma2_(x3, wB.y, acc[27]);
                const ulonglong2* wr2 = (const ulonglong2*)(wb + c * 16 + 8);
                ulonglong2 wC = wr2[0], wD = wr2[1];
                acc[4]  = fma2_(x0, wC.x, acc[4]);  acc[5]  = fma2_(x0, wC.y, acc[5]);
                acc[6]  = fma2_(x0, wD.x, acc[6]);  acc[7]  = fma2_(x0, wD.y, acc[7]);
                acc[12] = fma2_(x1, wC.x, acc[12]); acc[13] = fma2_(x1, wC.y, acc[13]);
                acc[14] = fma2_(x1, wD.x, acc[14]); acc[15] = fma2_(x1, wD.y, acc[15]);
                acc[20] = fma2_(x2, wC.x, acc[20]); acc[21] = fma2_(x2, wC.y, acc[21]);
                acc[22] = fma2_(x2, wD.x, acc[22]); acc[23] = fma2_(x2, wD.y, acc[23]);
                acc[28] = fma2_(x3, wC.x, acc[28]); acc[29] = fma2_(x3, wC.y, acc[29]);
                acc[30] = fma2_(x3, wD.x, acc[30]); acc[31] = fma2_(x3, wD.y, acc[31]);
            }
            __syncwarp();
#pragma unroll
            for (int j = 0; j < 4; j++) {
                float* row = xg + (4 * q + j) * RPITCH;
#pragma unroll
                for (int u2 = 0; u2 < 8; u2++) {
                    float a0, a1;
                    upk2(acc[j * 8 + u2], a0, a1);
                    int oc = chb + 2 * u2;
                    float v0 = __fadd_rn(__fmul_rn(a0, sc0[oc]),     bi0[oc]);
                    float v1 = __fadd_rn(__fmul_rn(a1, sc0[oc + 1]), bi0[oc + 1]);
                    row[oc]     = fmaxf(v0, 0.0f);
                    row[oc + 1] = fmaxf(v1, 0.0f);
                }
            }
            __syncwarp();
        }

        // ---- layer 1: 64 -> 64 ----
        {
            const float* wb = w1v + s * W1SL;
#pragma unroll
            for (int i = 0; i < 32; i++) acc[i] = 0ull;
#pragma unroll 1
            for (int c = 0; c < 64; c++) {
                const ulonglong2* wr = (const ulonglong2*)(wb + c * 16);
                ulonglong2 wA = wr[0], wB = wr[1];
                unsigned long long x0 = pk2(xg[(4 * q + 0) * RPITCH + c], xg[(4 * q + 0) * RPITCH + c]);
                unsigned long long x1 = pk2(xg[(4 * q + 1) * RPITCH + c], xg[(4 * q + 1) * RPITCH + c]);
                unsigned long long x2 = pk2(xg[(4 * q + 2) * RPITCH + c], xg[(4 * q + 2) * RPITCH + c]);
                unsigned long long x3 = pk2(xg[(4 * q + 3) * RPITCH + c], xg[(4 * q + 3) * RPITCH + c]);
                acc[0]  = fma2_(x0, wA.x, acc[0]);  acc[1]  = fma2_(x0, wA.y, acc[1]);
                acc[2]  = fma2_(x0, wB.x, acc[2]);  acc[3]  = fma2_(x0, wB.y, acc[3]);
                acc[8]  = fma2_(x1, wA.x, acc[8]);  acc[9]  = fma2_(x1, wA.y, acc[9]);
                acc[10] = fma2_(x1, wB.x, acc[10]); acc[11] = fma2_(x1, wB.y, acc[11]);
                acc[16] = fma2_(x2, wA.x, acc[16]); acc[17] = fma2_(x2, wA.y, acc[17]);
                acc[18] = fma2_(x2, wB.x, acc[18]); acc[19] = fma2_(x2, wB.y, acc[19]);
                acc[24] = fma2_(x3, wA.x, acc[24]); acc[25] = fma2_(x3, wA.y, acc[25]);
                acc[26] = fma2_(x3, wB.x, acc[26]); acc[27] = fma2_(x3, wB.y, acc[27]);
                const ulonglong2* wr2 = (const ulonglong2*)(wb + c * 16 + 8);
                ulonglong2 wC = wr2[0], wD = wr2[1];
                acc[4]  = fma2_(x0, wC.x, acc[4]);  acc[5]  = fma2_(x0, wC.y, acc[5]);
                acc[6]  = fma2_(x0, wD.x, acc[6]);  acc[7]  = fma2_(x0, wD.y, acc[7]);
                acc[12] = fma2_(x1, wC.x, acc[12]); acc[13] = fma2_(x1, wC.y, acc[13]);
                acc[14] = fma2_(x1, wD.x, acc[14]); acc[15] = fma2_(x1, wD.y, acc[15]);
                acc[20] = fma2_(x2, wC.x, acc[20]); acc[21] = fma2_(x2, wC.y, acc[21]);
                acc[22] = fma2_(x2, wD.x, acc[22]); acc[23] = fma2_(x2, wD.y, acc[23]);
                acc[28] = fma2_(x3, wC.x, acc[28]); acc[29] = fma2_(x3, wC.y, acc[29]);
                acc[30] = fma2_(x3, wD.x, acc[30]); acc[31] = fma2_(x3, wD.y, acc[31]);
            }
            __syncwarp();
#pragma unroll
            for (int j = 0; j < 4; j++) {
                float* row = xg + (4 * q + j) * RPITCH;
#pragma unroll
                for (int u2 = 0; u2 < 8; u2++) {
                    float a0, a1;
                    upk2(acc[j * 8 + u2], a0, a1);
                    int oc = chb + 2 * u2;
                    float v0 = __fadd_rn(__fmul_rn(a0, sc1[oc]),     bi1[oc]);
                    float v1 = __fadd_rn(__fmul_rn(a1, sc1[oc + 1]), bi1[oc + 1]);
                    row[oc]     = fmaxf(v0, 0.0f);
                    row[oc + 1] = fmaxf(v1, 0.0f);
                }
            }
            __syncwarp();
        }

        // ---- layer 2: 64 -> 128 in 2 rounds; reduce-scatter maxpool ----
        const size_t outbase = (size_t)b * 128 * NPOINT + sidx;
#pragma unroll 1
        for (int r = 0; r < 2; r++) {
            const int p = s + 4 * r;              // slice 0..7
            const float* wb = w2v + p * W2SL;
#pragma unroll
            for (int i = 0; i < 32; i++) acc[i] = 0ull;
#pragma unroll 1
            for (int c = 0; c < 64; c++) {
                const ulonglong2* wr = (const ulonglong2*)(wb + c * 16);
                ulonglong2 wA = wr[0], wB = wr[1];
                unsigned long long x0 = pk2(xg[(4 * q + 0) * RPITCH + c], xg[(4 * q + 0) * RPITCH + c]);
                unsigned long long x1 = pk2(xg[(4 * q + 1) * RPITCH + c], xg[(4 * q + 1) * RPITCH + c]);
                unsigned long long x2 = pk2(xg[(4 * q + 2) * RPITCH + c], xg[(4 * q + 2) * RPITCH + c]);
                unsigned long long x3 = pk2(xg[(4 * q + 3) * RPITCH + c], xg[(4 * q + 3) * RPITCH + c]);
                acc[0]  = fma2_(x0, wA.x, acc[0]);  acc[1]  = fma2_(x0, wA.y, acc[1]);
                acc[2]  = fma2_(x0, wB.x, acc[2]);  acc[3]  = fma2_(x0, wB.y, acc[3]);
                acc[8]  = fma2_(x1, wA.x, acc[8]);  acc[9]  = fma2_(x1, wA.y, acc[9]);
                acc[10] = fma2_(x1, wB.x, acc[10]); acc[11] = fma2_(x1, wB.y, acc[11]);
                acc[16] = fma2_(x2, wA.x, acc[16]); acc[17] = fma2_(x2, wA.y, acc[17]);
                acc[18] = fma2_(x2, wB.x, acc[18]); acc[19] = fma2_(x2, wB.y, acc[19]);
                acc[24] = fma2_(x3, wA.x, acc[24]); acc[25] = fma2_(x3, wA.y, acc[25]);
                acc[26] = fma2_(x3, wB.x, acc[26]); acc[27] = fma2_(x3, wB.y, acc[27]);
                const ulonglong2* wr2 = (const ulonglong2*)(wb + c * 16 + 8);
                ulonglong2 wC = wr2[0], wD = wr2[1];
                acc[4]  = fma2_(x0, wC.x, acc[4]);  acc[5]  = fma2_(x0, wC.y, acc[5]);
                acc[6]  = fma2_(x0, wD.x, acc[6]);  acc[7]  = fma2_(x0, wD.y, acc[7]);
                acc[12] = fma2_(x1, wC.x, acc[12]); acc[13] = fma2_(x1, wC.y, acc[13]);
                acc[14] = fma2_(x1, wD.x, acc[14]); acc[15] = fma2_(x1, wD.y, acc[15]);
                acc[20] = fma2_(x2, wC.x, acc[20]); acc[21] = fma2_(x2, wC.y, acc[21]);
                acc[22] = fma2_(x2, wD.x, acc[22]); acc[23] = fma2_(x2, wD.y, acc[23]);
                acc[28] = fma2_(x3, wC.x, acc[28]); acc[29] = fma2_(x3, wC.y, acc[29]);
                acc[30] = fma2_(x3, wD.x, acc[30]); acc[31] = fma2_(x3, wD.y, acc[31]);
            }
            float vm[16];
#pragma unroll
            for (int u2 = 0; u2 < 8; u2++) {
                int oc = p * 16 + 2 * u2;
                float scA = sc2[oc], biA = bi2[oc], scB = sc2[oc + 1], biB = bi2[oc + 1];
                float m0 = 0.0f, m1 = 0.0f;   // relu floor
#pragma unroll
                for (int j = 0; j < 4; j++) {
                    float a0, a1;
                    upk2(acc[j * 8 + u2], a0, a1);
                    float v0 = __fadd_rn(__fmul_rn(a0, scA), biA);
                    float v1 = __fadd_rn(__fmul_rn(a1, scB), biB);
                    m0 = fmaxf(m0, fmaxf(v0, 0.0f));
                    m1 = fmaxf(m1, fmaxf(v1, 0.0f));
                }
                vm[2 * u2] = m0; vm[2 * u2 + 1] = m1;
            }
            float B8[8];
#pragma unroll
            for (int i = 0; i < 8; i++) {
                float snd = q2 ? vm[i] : vm[8 + i];
                float got = __shfl_xor_sync(0xffffffffu, snd, 4);
                float kp  = q2 ? vm[8 + i] : vm[i];
                B8[i] = fmaxf(kp, got);
            }
            float C4[4];
#pragma unroll
            for (int i = 0; i < 4; i++) {
                float snd = q1 ? B8[i] : B8[4 + i];
                float got = __shfl_xor_sync(0xffffffffu, snd, 2);
                float kp  = q1 ? B8[4 + i] : B8[i];
                C4[i] = fmaxf(kp, got);
            }
            float D0, D1;
            {
                float snd = q0 ? C4[0] : C4[2];
                float got = __shfl_xor_sync(0xffffffffu, snd, 1);
                float kp  = q0 ? C4[2] : C4[0];
                D0 = fmaxf(kp, got);
                snd = q0 ? C4[1] : C4[3];
                got = __shfl_xor_sync(0xffffffffu, snd, 1);
                kp  = q0 ? C4[3] : C4[1];
                D1 = fmaxf(kp, got);
            }
            const int ch = p * 16 + 2 * q;
            outfeat[outbase + (size_t)ch * NPOINT]       = D0;
            outfeat[outbase + (size_t)(ch + 1) * NPOINT] = D1;
        }

        u = nxt;
    }
}

// ==================================================================
// launch
// ==================================================================
extern "C" void kernel_launch(void* const* d_in, const int* in_sizes, int n_in,
                              void* d_out, int out_size)
{
    (void)in_sizes; (void)n_in; (void)out_size;
    const float* xyz  = (const float*)d_in[0];
    const float* feat = (const float*)d_in[1];
    const float* w0 = (const float*)d_in[2];
    const float* s0 = (const float*)d_in[3];
    const float* b0 = (const float*)d_in[4];
    const float* w1 = (const float*)d_in[5];
    const float* s1 = (const float*)d_in[6];
    const float* b1 = (const float*)d_in[7];
    const float* w2 = (const float*)d_in[8];
    const float* s2 = (const float*)d_in[9];
    const float* b2 = (const float*)d_in[10];

    float* out     = (float*)d_out;
    float* newxyz  = out;                            // (B, NPOINT, 3)
    float* outfeat = out + (size_t)BB * NPOINT * 3;  // (B, 128, NPOINT)

    const int FUSED_SMEM = (4 * W0SL + 4 * W1SL + 8 * W2SL + 512 +
                            16 * 32 * RPITCH) * 4;   // ~205,824 B
    cudaFuncSetAttribute(fused_kernel, cudaFuncAttributeMaxDynamicSharedMemorySize,
                         FUSED_SMEM);

    resetk<<<1, 32>>>();
    fused_kernel<<<BB + MLP_BLOCKS, 512, FUSED_SMEM>>>(
        xyz, feat, w0, s0, b0, w1, s1, b1, w2, s2, b2, newxyz, outfeat);
}

// round 16
// speedup vs baseline: 1.6585x; 1.0808x over previous
#include <cuda_runtime.h>
#include <cstdint>

#define BB       8
#define NN       8192
#define NPOINT   1024
#define NSAMPLE  32
#define CFEAT    64
#define CIN0     67      // 3 + 64

#define MLP_BLOCKS 140                  // blocks 8..147 of the fused grid
#define NWARPS_TOT (MLP_BLOCKS * 16)    // 2240 consumer warps

// ------------------------------------------------------------------
// scratch (no allocations allowed)
// ------------------------------------------------------------------
__device__ unsigned g_prog[BB * 32];    // per-batch FPS progress, 128B padded
__device__ unsigned g_mlp_ctr;          // work-steal counter (reset each run)

// ------------------------------------------------------------------
// packed f32x2 helpers (Blackwell sm_103a) — add/mul/fma only
// ------------------------------------------------------------------
__device__ __forceinline__ unsigned long long pk2(float lo, float hi) {
    unsigned long long r;
    asm("mov.b64 %0, {%1, %2};" : "=l"(r) : "f"(lo), "f"(hi));
    return r;
}
__device__ __forceinline__ void upk2(unsigned long long v, float& lo, float& hi) {
    asm("mov.b64 {%0, %1}, %2;" : "=f"(lo), "=f"(hi) : "l"(v));
}
__device__ __forceinline__ unsigned long long add2_(unsigned long long a, unsigned long long b) {
    unsigned long long r;
    asm("add.rn.f32x2 %0, %1, %2;" : "=l"(r) : "l"(a), "l"(b));
    return r;
}
__device__ __forceinline__ unsigned long long mul2_(unsigned long long a, unsigned long long b) {
    unsigned long long r;
    asm("mul.rn.f32x2 %0, %1, %2;" : "=l"(r) : "l"(a), "l"(b));
    return r;
}
__device__ __forceinline__ unsigned long long fma2_(unsigned long long a, unsigned long long b,
                                                    unsigned long long c) {
    unsigned long long r;
    asm("fma.rn.f32x2 %0, %1, %2, %3;" : "=l"(r) : "l"(a), "l"(b), "l"(c));
    return r;
}
__device__ __forceinline__ unsigned ld_acq32(const unsigned* p) {
    unsigned v;
    asm volatile("ld.acquire.gpu.b32 %0, [%1];" : "=r"(v) : "l"(p) : "memory");
    return v;
}
__device__ __forceinline__ void st_rel32(unsigned* p, unsigned v) {
    asm volatile("st.release.gpu.b32 [%0], %1;" :: "l"(p), "r"(v) : "memory");
}

// ==================================================================
// Kernel 0: reset progress + steal counter (graph replays would
// otherwise see stale g_prog and read the poisoned output buffer).
// ==================================================================
__global__ void resetk()
{
    if (threadIdx.x < BB) g_prog[threadIdx.x * 32] = 0u;
    if (threadIdx.x == 0) g_mlp_ctr = NWARPS_TOT;
}

// ==================================================================
// Fused kernel (R13 configuration — measured best, 630.4 µs):
//   blocks 0..7   : FPS producers, single-CTA per batch; progress
//                   published every 8 iterations (release fence off
//                   the per-iter critical path).
//   blocks 8..147 : persistent MLP consumer warps with work stealing
//                   and exponential-backoff acquire polling.
// FPS warp argmax: equality scan vs the thread's OWN max (overlaps
// the REDUX), ballot/ffs/shfl for warp-first-index; block combine via
// REDUX max + REDUX min over (index | tie mask).
// ==================================================================
#define FPS_T 512
#define FPS_P (NN / FPS_T)   // 16
#define MLP_T   512
#define RPITCH  67               // 67 % 32 = 3 -> 8 samples hit 8 banks
#define W0SL    (CIN0 * 16 + 4)  // 1076 floats per slice (skewed)
#define W1SL    (64 * 16 + 4)    // 1028
#define W2SL    (64 * 16 + 4)    // 1028

__global__ void __launch_bounds__(512, 1)
fused_kernel(const float* __restrict__ xyz, const float* __restrict__ feat,
             const float* __restrict__ w0, const float* __restrict__ s0g, const float* __restrict__ b0g,
             const float* __restrict__ w1, const float* __restrict__ s1g, const float* __restrict__ b1g,
             const float* __restrict__ w2, const float* __restrict__ s2g, const float* __restrict__ b2g,
             float* __restrict__ newxyz, float* __restrict__ outfeat)
{
    extern __shared__ float sm[];

    if (blockIdx.x < BB) {
        // ================= FPS producer =================
        float* sx = sm;
        float* sy = sm + NN;
        float* sz = sm + 2 * NN;
        unsigned* wv = (unsigned*)(sm + 3 * NN);   // [2][16]
        unsigned* wi = wv + 32;                    // [2][16]

        const int b = blockIdx.x;
        const float* bx = xyz + (size_t)b * NN * 3;
        float* out = newxyz + (size_t)b * NPOINT * 3;
        unsigned* prog = &g_prog[b * 32];
        const int t = threadIdx.x;
        const int lane = t & 31;
        const int warp = t >> 5;

        unsigned long long px2[FPS_P / 2], py2[FPS_P / 2], pz2[FPS_P / 2];
        float mind[FPS_P];
#pragma unroll
        for (int k = 0; k < FPS_P / 2; k++) {
            int i0 = t * FPS_P + 2 * k;
            int i1 = i0 + 1;
            float x0 = bx[i0 * 3 + 0], y0 = bx[i0 * 3 + 1], z0 = bx[i0 * 3 + 2];
            float x1 = bx[i1 * 3 + 0], y1 = bx[i1 * 3 + 1], z1 = bx[i1 * 3 + 2];
            px2[k] = pk2(x0, x1); py2[k] = pk2(y0, y1); pz2[k] = pk2(z0, z1);
            sx[i0] = x0; sy[i0] = y0; sz[i0] = z0;
            sx[i1] = x1; sy[i1] = y1; sz[i1] = z1;
            mind[2 * k] = 1e10f; mind[2 * k + 1] = 1e10f;
        }
        __syncthreads();

        float qx = sx[0], qy = sy[0], qz = sz[0];
        if (t == 0) { out[0] = qx; out[1] = qy; out[2] = qz; }

        for (int it = 1; it < NPOINT; it++) {
            const unsigned long long nqx = pk2(-qx, -qx);
            const unsigned long long nqy = pk2(-qy, -qy);
            const unsigned long long nqz = pk2(-qz, -qz);
            float vloc = -1.0f;
#pragma unroll
            for (int k = 0; k < FPS_P / 2; k++) {
                unsigned long long dx = add2_(px2[k], nqx);
                unsigned long long dy = add2_(py2[k], nqy);
                unsigned long long dz = add2_(pz2[k], nqz);
                unsigned long long d2 = add2_(add2_(mul2_(dx, dx), mul2_(dy, dy)),
                                              mul2_(dz, dz));
                float d0, d1;
                upk2(d2, d0, d1);
                float m0 = fminf(mind[2 * k], d0);
                float m1 = fminf(mind[2 * k + 1], d1);
                mind[2 * k] = m0;
                mind[2 * k + 1] = m1;
                vloc = fmaxf(vloc, fmaxf(m0, m1));
            }
            // first local index attaining the THREAD max (overlaps REDUX)
            unsigned idxl = 0xffffffffu;
#pragma unroll
            for (int j = FPS_P - 1; j >= 0; j--)
                if (mind[j] == vloc) idxl = t * FPS_P + j;

            unsigned vb = __float_as_uint(vloc);
            unsigned wmax = __reduce_max_sync(0xffffffffu, vb);
            // lowest lane attaining wmax holds the lowest index
            unsigned act = __ballot_sync(0xffffffffu, vb == wmax);
            int src = __ffs(act) - 1;
            unsigned widx = __shfl_sync(0xffffffffu, idxl, src);

            const int par = (it & 1) << 4;
            if (lane == 0) { wv[par + warp] = wmax; wi[par + warp] = widx; }
            __syncthreads();

            unsigned bvv = wv[par + (lane & 15)];
            unsigned bii = wi[par + (lane & 15)];
            unsigned vmax = __reduce_max_sync(0xffffffffu, bvv);
            unsigned bi   = __reduce_min_sync(0xffffffffu,
                                              (bvv == vmax) ? bii : 0xffffffffu);

            qx = sx[bi]; qy = sy[bi]; qz = sz[bi];
            if (t == 0) {
                out[it * 3 + 0] = qx;
                out[it * 3 + 1] = qy;
                out[it * 3 + 2] = qz;
                // batched release: fence cost off the per-iter path
                if ((it & 7) == 7 || it == NPOINT - 1)
                    st_rel32(prog, (unsigned)it + 1u);
            }
        }
        return;
    }

    // ================= MLP consumer =================
    float* w0v = sm;                    // 4 slices x W0SL
    float* w1v = w0v + 4 * W0SL;        // 4 slices x W1SL
    float* w2v = w1v + 4 * W1SL;        // 8 slices x W2SL
    float* sc0 = w2v + 8 * W2SL;
    float* bi0 = sc0 + 64;
    float* sc1 = bi0 + 64;
    float* bi1 = sc1 + 64;
    float* sc2 = bi1 + 64;              // 128
    float* bi2 = sc2 + 128;             // 128
    float* xr  = bi2 + 128;             // 16 * 32 * RPITCH

    const int t = threadIdx.x;
    const int lane = t & 31;
    const int g = t >> 5;               // warp within block
    const int q = lane & 7;             // sample quad id (samples 4q..4q+3)
    const int s = lane >> 3;            // channel-slice id (0..3)

    // ---- weight load: slice-major [slice][c][16] with +4 skew ----
    for (int i = t; i < 4 * CIN0 * 16; i += MLP_T) {
        int sl = i / (CIN0 * 16), r = i - sl * (CIN0 * 16);
        int c = r >> 4, k = r & 15;
        w0v[sl * W0SL + r] = w0[(sl * 16 + k) * CIN0 + c];
    }
    for (int i = t; i < 4 * 64 * 16; i += MLP_T) {
        int sl = i >> 10, r = i & 1023;
        int c = r >> 4, k = r & 15;
        w1v[sl * W1SL + r] = w1[(sl * 16 + k) * 64 + c];
    }
    for (int i = t; i < 8 * 64 * 16; i += MLP_T) {
        int sl = i >> 10, r = i & 1023;
        int c = r >> 4, k = r & 15;
        w2v[sl * W2SL + r] = w2[(sl * 16 + k) * 64 + c];
    }
    if (t < 64)  { sc0[t] = s0g[t]; bi0[t] = b0g[t]; sc1[t] = s1g[t]; bi1[t] = b1g[t]; }
    if (t < 128) { sc2[t] = s2g[t]; bi2[t] = b2g[t]; }
    __syncthreads();

    float* xg = xr + g * 32 * RPITCH;
    int* idxbuf = (int*)xg;             // 32 ints, used before gather overwrites
    const int q2 = (q >> 2) & 1, q1 = (q >> 1) & 1, q0 = q & 1;

    unsigned u = (blockIdx.x - BB) * 16 + g;   // initial unit = global warp id

    while (u < BB * NPOINT) {
        // prefetch next steal (latency hidden behind this unit)
        unsigned nxt;
        if (lane == 0) nxt = atomicAdd(&g_mlp_ctr, 1u);
        nxt = __shfl_sync(0xffffffffu, nxt, 0);

        const int sidx = (int)(u >> 3);       // s-major readiness order
        const int b    = (int)(u & 7);
        const int gi   = b * NPOINT + sidx;

        // ---- wait for FPS(b) to publish center sidx (backoff poll) ----
        {
            const unsigned* pp = &g_prog[b * 32];
            unsigned pv = ld_acq32(pp);
            int slp = 128;
            while (pv <= (unsigned)sidx) {
                __nanosleep(slp);
                if (slp < 1024) slp <<= 1;
                pv = ld_acq32(pp);
            }
        }

        const float cx = newxyz[gi * 3 + 0];
        const float cy = newxyz[gi * 3 + 1];
        const float cz = newxyz[gi * 3 + 2];

        // ---- in-warp ball query (bit-exact mask arithmetic) ----
        int myidx;
        {
            const float* bx = xyz + (size_t)b * NN * 3;
            const float R2 = (float)0.04;
            int cnt = 0, firstIdx = 0;
            for (int base = 0; base < NN; base += 32) {
                const int i = base + lane;
                float dx = __fsub_rn(bx[i * 3 + 0], cx);
                float dy = __fsub_rn(bx[i * 3 + 1], cy);
                float dz = __fsub_rn(bx[i * 3 + 2], cz);
                float d  = __fadd_rn(__fadd_rn(__fmul_rn(dx, dx), __fmul_rn(dy, dy)),
                                     __fmul_rn(dz, dz));
                bool in = d < R2;
                unsigned mask = __ballot_sync(0xffffffffu, in);
                if (mask) {
                    if (cnt == 0) firstIdx = base + (__ffs(mask) - 1);
                    if (in) {
                        int slot = cnt + __popc(mask & ((1u << lane) - 1u));
                        if (slot < NSAMPLE) idxbuf[slot] = i;
                    }
                    cnt += __popc(mask);
                    if (cnt >= NSAMPLE) break;
                }
            }
            __syncwarp();
            myidx = (lane < cnt) ? idxbuf[lane] : ((cnt > 0) ? firstIdx : 0);
            __syncwarp();   // all reads done before gather overwrites idxbuf
        }

        // ---- gather: this thread fills rows of its 4 samples ----
#pragma unroll
        for (int j = 0; j < 4; j++) {
            const int n = 4 * q + j;
            const int pi = __shfl_sync(0xffffffffu, myidx, n);
            float* row = xg + n * RPITCH;
            const float* prow = xyz + ((size_t)b * NN + pi) * 3;
            row[0] = __fsub_rn(prow[0], cx);
            row[1] = __fsub_rn(prow[1], cy);
            row[2] = __fsub_rn(prow[2], cz);
            const float4* frow = (const float4*)(feat + ((size_t)b * NN + pi) * CFEAT);
#pragma unroll
            for (int k = 0; k < 16; k++) {
                float4 f = frow[k];
                row[3 + 4 * k + 0] = f.x;
                row[3 + 4 * k + 1] = f.y;
                row[3 + 4 * k + 2] = f.z;
                row[3 + 4 * k + 3] = f.w;
            }
        }
        __syncwarp();

        unsigned long long acc[32];
        const int chb = s * 16;

        // ---- layer 0: 67 -> 64 ----
        {
            const float* wb = w0v + s * W0SL;
#pragma unroll
            for (int i = 0; i < 32; i++) acc[i] = 0ull;
#pragma unroll 1
            for (int c = 0; c < CIN0; c++) {
                const ulonglong2* wr = (const ulonglong2*)(wb + c * 16);
                ulonglong2 wA = wr[0], wB = wr[1];
                unsigned long long x0 = pk2(xg[(4 * q + 0) * RPITCH + c], xg[(4 * q + 0) * RPITCH + c]);
                unsigned long long x1 = pk2(xg[(4 * q + 1) * RPITCH + c], xg[(4 * q + 1) * RPITCH + c]);
                unsigned long long x2 = pk2(xg[(4 * q + 2) * RPITCH + c], xg[(4 * q + 2) * RPITCH + c]);
                unsigned long long x3 = pk2(xg[(4 * q + 3) * RPITCH + c], xg[(4 * q + 3) * RPITCH + c]);
                acc[0]  = fma2_(x0, wA.x, acc[0]);  acc[1]  = fma2_(x0, wA.y, acc[1]);
                acc[2]  = fma2_(x0, wB.x, acc[2]);  acc[3]  = fma2_(x0, wB.y, acc[3]);
                acc[8]  = fma2_(x1, wA.x, acc[8]);  acc[9]  = fma2_(x1, wA.y, acc[9]);
                acc[10] = fma2_(x1, wB.x, acc[10]); acc[11] = fma2_(x1, wB.y, acc[11]);
                acc[16] = fma2_(x2, wA.x, acc[16]); acc[17] = fma2_(x2, wA.y, acc[17]);
                acc[18] = fma2_(x2, wB.x, acc[18]); acc[19] = fma2_(x2, wB.y, acc[19]);
                acc[24] = fma2_(x3, wA.x, acc[24]); acc[25] = fma2_(x3, wA.y, acc[25]);
                acc[26] = fma2_(x3, wB.x, acc[26]); acc[27] = fma2_(x3, wB.y, acc[27]);
                const ulonglong2* wr2 = (const ulonglong2*)(wb + c * 16 + 8);
                ulonglong2 wC = wr2[0], wD = wr2[1];
                acc[4]  = fma2_(x0, wC.x, acc[4]);  acc[5]  = fma2_(x0, wC.y, acc[5]);
                acc[6]  = fma2_(x0, wD.x, acc[6]);  acc[7]  = fma2_(x0, wD.y, acc[7]);
                acc[12] = fma2_(x1, wC.x, acc[12]); acc[13] = fma2_(x1, wC.y, acc[13]);
                acc[14] = fma2_(x1, wD.x, acc[14]); acc[15] = fma2_(x1, wD.y, acc[15]);
                acc[20] = fma2_(x2, wC.x, acc[20]); acc[21] = fma2_(x2, wC.y, acc[21]);
                acc[22] = fma2_(x2, wD.x, acc[22]); acc[23] = fma2_(x2, wD.y, acc[23]);
                acc[28] = fma2_(x3, wC.x, acc[28]); acc[29] = fma2_(x3, wC.y, acc[29]);
                acc[30] = fma2_(x3, wD.x, acc[30]); acc[31] = fma2_(x3, wD.y, acc[31]);
            }
            __syncwarp();
#pragma unroll
            for (int j = 0; j < 4; j++) {
                float* row = xg + (4 * q + j) * RPITCH;
#pragma unroll
                for (int u2 = 0; u2 < 8; u2++) {
                    float a0, a1;
                    upk2(acc[j * 8 + u2], a0, a1);
                    int oc = chb + 2 * u2;
                    float v0 = __fadd_rn(__fmul_rn(a0, sc0[oc]),     bi0[oc]);
                    float v1 = __fadd_rn(__fmul_rn(a1, sc0[oc + 1]), bi0[oc + 1]);
                    row[oc]     = fmaxf(v0, 0.0f);
                    row[oc + 1] = fmaxf(v1, 0.0f);
                }
            }
            __syncwarp();
        }

        // ---- layer 1: 64 -> 64 ----
        {
            const float* wb = w1v + s * W1SL;
#pragma unroll
            for (int i = 0; i < 32; i++) acc[i] = 0ull;
#pragma unroll 1
            for (int c = 0; c < 64; c++) {
                const ulonglong2* wr = (const ulonglong2*)(wb + c * 16);
                ulonglong2 wA = wr[0], wB = wr[1];
                unsigned long long x0 = pk2(xg[(4 * q + 0) * RPITCH + c], xg[(4 * q + 0) * RPITCH + c]);
                unsigned long long x1 = pk2(xg[(4 * q + 1) * RPITCH + c], xg[(4 * q + 1) * RPITCH + c]);
                unsigned long long x2 = pk2(xg[(4 * q + 2) * RPITCH + c], xg[(4 * q + 2) * RPITCH + c]);
                unsigned long long x3 = pk2(xg[(4 * q + 3) * RPITCH + c], xg[(4 * q + 3) * RPITCH + c]);
                acc[0]  = fma2_(x0, wA.x, acc[0]);  acc[1]  = fma2_(x0, wA.y, acc[1]);
                acc[2]  = fma2_(x0, wB.x, acc[2]);  acc[3]  = fma2_(x0, wB.y, acc[3]);
                acc[8]  = fma2_(x1, wA.x, acc[8]);  acc[9]  = fma2_(x1, wA.y, acc[9]);
                acc[10] = fma2_(x1, wB.x, acc[10]); acc[11] = fma2_(x1, wB.y, acc[11]);
                acc[16] = fma2_(x2, wA.x, acc[16]); acc[17] = fma2_(x2, wA.y, acc[17]);
                acc[18] = fma2_(x2, wB.x, acc[18]); acc[19] = fma2_(x2, wB.y, acc[19]);
                acc[24] = fma2_(x3, wA.x, acc[24]); acc[25] = fma2_(x3, wA.y, acc[25]);
                acc[26] = fma2_(x3, wB.x, acc[26]); acc[27] = fma2_(x3, wB.y, acc[27]);
                const ulonglong2* wr2 = (const ulonglong2*)(wb + c * 16 + 8);
                ulonglong2 wC = wr2[0], wD = wr2[1];
                acc[4]  = fma2_(x0, wC.x, acc[4]);  acc[5]  = fma2_(x0, wC.y, acc[5]);
                acc[6]  = fma2_(x0, wD.x, acc[6]);  acc[7]  = fma2_(x0, wD.y, acc[7]);
                acc[12] = fma2_(x1, wC.x, acc[12]); acc[13] = fma2_(x1, wC.y, acc[13]);
                acc[14] = fma2_(x1, wD.x, acc[14]); acc[15] = fma2_(x1, wD.y, acc[15]);
                acc[20] = fma2_(x2, wC.x, acc[20]); acc[21] = fma2_(x2, wC.y, acc[21]);
                acc[22] = fma2_(x2, wD.x, acc[22]); acc[23] = fma2_(x2, wD.y, acc[23]);
                acc[28] = fma2_(x3, wC.x, acc[28]); acc[29] = fma2_(x3, wC.y, acc[29]);
                acc[30] = fma2_(x3, wD.x, acc[30]); acc[31] = fma2_(x3, wD.y, acc[31]);
            }
            __syncwarp();
#pragma unroll
            for (int j = 0; j < 4; j++) {
                float* row = xg + (4 * q + j) * RPITCH;
#pragma unroll
                for (int u2 = 0; u2 < 8; u2++) {
                    float a0, a1;
                    upk2(acc[j * 8 + u2], a0, a1);
                    int oc = chb + 2 * u2;
                    float v0 = __fadd_rn(__fmul_rn(a0, sc1[oc]),     bi1[oc]);
                    float v1 = __fadd_rn(__fmul_rn(a1, sc1[oc + 1]), bi1[oc + 1]);
                    row[oc]     = fmaxf(v0, 0.0f);
                    row[oc + 1] = fmaxf(v1, 0.0f);
                }
            }
            __syncwarp();
        }

        // ---- layer 2: 64 -> 128 in 2 rounds; reduce-scatter maxpool ----
        const size_t outbase = (size_t)b * 128 * NPOINT + sidx;
#pragma unroll 1
        for (int r = 0; r < 2; r++) {
            const int p = s + 4 * r;              // slice 0..7
            const float* wb = w2v + p * W2SL;
#pragma unroll
            for (int i = 0; i < 32; i++) acc[i] = 0ull;
#pragma unroll 1
            for (int c = 0; c < 64; c++) {
                const ulonglong2* wr = (const ulonglong2*)(wb + c * 16);
                ulonglong2 wA = wr[0], wB = wr[1];
                unsigned long long x0 = pk2(xg[(4 * q + 0) * RPITCH + c], xg[(4 * q + 0) * RPITCH + c]);
                unsigned long long x1 = pk2(xg[(4 * q + 1) * RPITCH + c], xg[(4 * q + 1) * RPITCH + c]);
                unsigned long long x2 = pk2(xg[(4 * q + 2) * RPITCH + c], xg[(4 * q + 2) * RPITCH + c]);
                unsigned long long x3 = pk2(xg[(4 * q + 3) * RPITCH + c], xg[(4 * q + 3) * RPITCH + c]);
                acc[0]  = fma2_(x0, wA.x, acc[0]);  acc[1]  = fma2_(x0, wA.y, acc[1]);
                acc[2]  = fma2_(x0, wB.x, acc[2]);  acc[3]  = fma2_(x0, wB.y, acc[3]);
                acc[8]  = fma2_(x1, wA.x, acc[8]);  acc[9]  = fma2_(x1, wA.y, acc[9]);
                acc[10] = fma2_(x1, wB.x, acc[10]); acc[11] = fma2_(x1, wB.y, acc[11]);
                acc[16] = fma2_(x2, wA.x, acc[16]); acc[17] = fma2_(x2, wA.y, acc[17]);
                acc[18] = fma2_(x2, wB.x, acc[18]); acc[19] = fma2_(x2, wB.y, acc[19]);
                acc[24] = fma2_(x3, wA.x, acc[24]); acc[25] = fma2_(x3, wA.y, acc[25]);
                acc[26] = fma2_(x3, wB.x, acc[26]); acc[27] = fma2_(x3, wB.y, acc[27]);
                const ulonglong2* wr2 = (const ulonglong2*)(wb + c * 16 + 8);
                ulonglong2 wC = wr2[0], wD = wr2[1];
                acc[4]  = fma2_(x0, wC.x, acc[4]);  acc[5]  = fma2_(x0, wC.y, acc[5]);
                acc[6]  = fma2_(x0, wD.x, acc[6]);  acc[7]  = fma2_(x0, wD.y, acc[7]);
                acc[12] = fma2_(x1, wC.x, acc[12]); acc[13] = fma2_(x1, wC.y, acc[13]);
                acc[14] = fma2_(x1, wD.x, acc[14]); acc[15] = fma2_(x1, wD.y, acc[15]);
                acc[20] = fma2_(x2, wC.x, acc[20]); acc[21] = fma2_(x2, wC.y, acc[21]);
                acc[22] = fma2_(x2, wD.x, acc[22]); acc[23] = fma2_(x2, wD.y, acc[23]);
                acc[28] = fma2_(x3, wC.x, acc[28]); acc[29] = fma2_(x3, wC.y, acc[29]);
                acc[30] = fma2_(x3, wD.x, acc[30]); acc[31] = fma2_(x3, wD.y, acc[31]);
            }
            float vm[16];
#pragma unroll
            for (int u2 = 0; u2 < 8; u2++) {
                int oc = p * 16 + 2 * u2;
                float scA = sc2[oc], biA = bi2[oc], scB = sc2[oc + 1], biB = bi2[oc + 1];
                float m0 = 0.0f, m1 = 0.0f;   // relu floor
#pragma unroll
                for (int j = 0; j < 4; j++) {
                    float a0, a1;
                    upk2(acc[j * 8 + u2], a0, a1);
                    float v0 = __fadd_rn(__fmul_rn(a0, scA), biA);
                    float v1 = __fadd_rn(__fmul_rn(a1, scB), biB);
                    m0 = fmaxf(m0, fmaxf(v0, 0.0f));
                    m1 = fmaxf(m1, fmaxf(v1, 0.0f));
                }
                vm[2 * u2] = m0; vm[2 * u2 + 1] = m1;
            }
            float B8[8];
#pragma unroll
            for (int i = 0; i < 8; i++) {
                float snd = q2 ? vm[i] : vm[8 + i];
                float got = __shfl_xor_sync(0xffffffffu, snd, 4);
                float kp  = q2 ? vm[8 + i] : vm[i];
                B8[i] = fmaxf(kp, got);
            }
            float C4[4];
#pragma unroll
            for (int i = 0; i < 4; i++) {
                float snd = q1 ? B8[i] : B8[4 + i];
                float got = __shfl_xor_sync(0xffffffffu, snd, 2);
                float kp  = q1 ? B8[4 + i] : B8[i];
                C4[i] = fmaxf(kp, got);
            }
            float D0, D1;
            {
                float snd = q0 ? C4[0] : C4[2];
                float got = __shfl_xor_sync(0xffffffffu, snd, 1);
                float kp  = q0 ? C4[2] : C4[0];
                D0 = fmaxf(kp, got);
                snd = q0 ? C4[1] : C4[3];
                got = __shfl_xor_sync(0xffffffffu, snd, 1);
                kp  = q0 ? C4[3] : C4[1];
                D1 = fmaxf(kp, got);
            }
            const int ch = p * 16 + 2 * q;
            outfeat[outbase + (size_t)ch * NPOINT]       = D0;
            outfeat[outbase + (size_t)(ch + 1) * NPOINT] = D1;
        }

        u = nxt;
    }
}

// ==================================================================
// launch
// ==================================================================
extern "C" void kernel_launch(void* const* d_in, const int* in_sizes, int n_in,
                              void* d_out, int out_size)
{
    (void)in_sizes; (void)n_in; (void)out_size;
    const float* xyz  = (const float*)d_in[0];
    const float* feat = (const float*)d_in[1];
    const float* w0 = (const float*)d_in[2];
    const float* s0 = (const float*)d_in[3];
    const float* b0 = (const float*)d_in[4];
    const float* w1 = (const float*)d_in[5];
    const float* s1 = (const float*)d_in[6];
    const float* b1 = (const float*)d_in[7];
    const float* w2 = (const float*)d_in[8];
    const float* s2 = (const float*)d_in[9];
    const float* b2 = (const float*)d_in[10];

    float* out     = (float*)d_out;
    float* newxyz  = out;                            // (B, NPOINT, 3)
    float* outfeat = out + (size_t)BB * NPOINT * 3;  // (B, 128, NPOINT)

    const int FUSED_SMEM = (4 * W0SL + 4 * W1SL + 8 * W2SL + 512 +
                            16 * 32 * RPITCH) * 4;   // ~205,824 B
    cudaFuncSetAttribute(fused_kernel, cudaFuncAttributeMaxDynamicSharedMemorySize,
                         FUSED_SMEM);

    resetk<<<1, 32>>>();
    fused_kernel<<<BB + MLP_BLOCKS, 512, FUSED_SMEM>>>(
        xyz, feat, w0, s0, b0, w1, s1, b1, w2, s2, b2, newxyz, outfeat);
}